// round 10
// baseline (speedup 1.0000x reference)
#include <cuda_runtime.h>

#define BATCH 4
#define HEADS 12
#define SEQ   2048
#define DK    64
#define TQ    64
#define TK    64
#define LDK   68   // K/Q smem pitch: 68 mod 32 = 4 -> banks 4*grp+tg, conflict-free
#define LDV   72   // V smem pitch:   72 mod 32 = 8 -> banks 8*tg+grp, conflict-free
#define LDC   66   // ctx reduce buffer pitch (even for float2)
#define FULLMASK 0xffffffffu

__device__ __forceinline__ float to_tf32(float x) {
    asm("cvt.rna.tf32.f32 %0, %0;" : "+f"(x));
    return x;
}

// D = A(16x8 tf32, row) * B(8x8 tf32, col) + D, fp32 accum
__device__ __forceinline__ void mma_tf32(float d[4], const unsigned a[4],
                                         unsigned b0, unsigned b1) {
    asm volatile(
        "mma.sync.aligned.m16n8k8.row.col.f32.tf32.tf32.f32 "
        "{%0,%1,%2,%3}, {%4,%5,%6,%7}, {%8,%9}, {%0,%1,%2,%3};"
        : "+f"(d[0]), "+f"(d[1]), "+f"(d[2]), "+f"(d[3])
        : "r"(a[0]), "r"(a[1]), "r"(a[2]), "r"(a[3]), "r"(b0), "r"(b1));
}

__global__ void __launch_bounds__(256)
attn_kernel(const float* __restrict__ Q, const float* __restrict__ K,
            const float* __restrict__ V, const float* __restrict__ M,
            float* __restrict__ ctx_out, float* __restrict__ attn_out)
{
    __shared__ float Ks[TK * LDK];      // Q staging, then K tile; ctx reduce buf at end
    __shared__ float Vs[TK * LDV];      // V tile
    __shared__ float s_sums[2 * TQ];
    __shared__ float s_inv[TQ];

    const int qt = blockIdx.x, h = blockIdx.y, b = blockIdx.z;
    const int tid  = threadIdx.x;
    const int warp = tid >> 5;
    const int lane = tid & 31;
    const int mg = warp >> 1;          // 4 m-groups: rows mg*16 .. +15
    const int ng = warp & 1;           // 2 n-groups: score cols ng*32 .. +31 (per kt tile)
    const int grp = lane >> 2;         // 0..7
    const int tg  = lane & 3;          // 0..3

    const size_t bh = (size_t)b * HEADS + h;
    const float* Qb = Q + (bh * SEQ + (size_t)qt * TQ) * DK;
    const float* Kb = K + bh * SEQ * DK;
    const float* Vb = V + bh * SEQ * DK;
    const float* Mb = M + ((size_t)b * SEQ + (size_t)qt * TQ) * SEQ;
    float* Ab = attn_out + (bh * SEQ + (size_t)qt * TQ) * SEQ;
    float* Cb = ctx_out  + (bh * SEQ + (size_t)qt * TQ) * DK;

    const int row0 = mg * 16 + grp;    // this lane's query rows within the tile
    const int row1 = row0 + 8;

    // ---- stage Q tile into Ks (tf32-rounded), hoist a-fragments to registers ----
    for (int i = tid; i < TQ * 16; i += 256) {
        int r = i >> 4, c = (i & 15) << 2;
        float4 v = *(const float4*)(Qb + (size_t)r * DK + c);
        Ks[r * LDK + c + 0] = to_tf32(v.x);
        Ks[r * LDK + c + 1] = to_tf32(v.y);
        Ks[r * LDK + c + 2] = to_tf32(v.z);
        Ks[r * LDK + c + 3] = to_tf32(v.w);
    }
    __syncthreads();

    unsigned qa[8][4];
    {
        const unsigned* Ku = (const unsigned*)Ks;
        #pragma unroll
        for (int kk = 0; kk < 8; ++kk) {
            qa[kk][0] = Ku[row0 * LDK + kk * 8 + tg];
            qa[kk][1] = Ku[row1 * LDK + kk * 8 + tg];
            qa[kk][2] = Ku[row0 * LDK + kk * 8 + tg + 4];
            qa[kk][3] = Ku[row1 * LDK + kk * 8 + tg + 4];
        }
    }
    __syncthreads();

    float ctxa[8][4];
    #pragma unroll
    for (int i = 0; i < 8; ++i)
        #pragma unroll
        for (int j = 0; j < 4; ++j) ctxa[i][j] = 0.f;

    float rsum_lo = 0.f, rsum_hi = 0.f;

    const int src0 = (lane & ~3) | (tg >> 1);
    const int src1 = src0 + 2;
    const bool odd = (tg & 1) != 0;

    for (int kt = 0; kt < SEQ / TK; ++kt) {
        // ---- prefetch mask (hide gmem latency behind tile load + MMA) ----
        float2 mk0[4], mk1[4];
        #pragma unroll
        for (int nt = 0; nt < 4; ++nt) {
            int col = kt * TK + ng * 32 + nt * 8 + 2 * tg;
            mk0[nt] = *(const float2*)(Mb + (size_t)row0 * SEQ + col);
            mk1[nt] = *(const float2*)(Mb + (size_t)row1 * SEQ + col);
        }

        // ---- load K and V tiles (tf32-rounded) ----
        for (int i = tid; i < TK * 16; i += 256) {
            int r = i >> 4, c = (i & 15) << 2;
            const float* kp = Kb + ((size_t)(kt * TK + r)) * DK + c;
            const float* vp = Vb + ((size_t)(kt * TK + r)) * DK + c;
            float4 kv = *(const float4*)kp;
            float4 vv = *(const float4*)vp;
            Ks[r * LDK + c + 0] = to_tf32(kv.x);
            Ks[r * LDK + c + 1] = to_tf32(kv.y);
            Ks[r * LDK + c + 2] = to_tf32(kv.z);
            Ks[r * LDK + c + 3] = to_tf32(kv.w);
            Vs[r * LDV + c + 0] = to_tf32(vv.x);
            Vs[r * LDV + c + 1] = to_tf32(vv.y);
            Vs[r * LDV + c + 2] = to_tf32(vv.z);
            Vs[r * LDV + c + 3] = to_tf32(vv.w);
        }
        __syncthreads();

        // ---- scores: D(m16 x n32) = Q . K^T, all in registers ----
        float sd[4][4];
        #pragma unroll
        for (int nt = 0; nt < 4; ++nt)
            #pragma unroll
            for (int j = 0; j < 4; ++j) sd[nt][j] = 0.f;

        const unsigned* Ku = (const unsigned*)Ks;
        #pragma unroll
        for (int kk = 0; kk < 8; ++kk) {
            #pragma unroll
            for (int nt = 0; nt < 4; ++nt) {
                int nr = ng * 32 + nt * 8 + grp;              // key seq position
                unsigned b0 = Ku[nr * LDK + kk * 8 + tg];
                unsigned b1 = Ku[nr * LDK + kk * 8 + tg + 4];
                mma_tf32(sd[nt], qa[kk], b0, b1);
            }
        }

        // ---- elementwise in registers: e = exp(s/8)*mask; rowsum; write attn ----
        #pragma unroll
        for (int nt = 0; nt < 4; ++nt) {
            int col = kt * TK + ng * 32 + nt * 8 + 2 * tg;
            float e0 = __expf(sd[nt][0] * 0.125f) * mk0[nt].x;
            float e1 = __expf(sd[nt][1] * 0.125f) * mk0[nt].y;
            float e2 = __expf(sd[nt][2] * 0.125f) * mk1[nt].x;
            float e3 = __expf(sd[nt][3] * 0.125f) * mk1[nt].y;
            rsum_lo += e0 + e1;
            rsum_hi += e2 + e3;
            *(float2*)(Ab + (size_t)row0 * SEQ + col) = make_float2(e0, e1);
            *(float2*)(Ab + (size_t)row1 * SEQ + col) = make_float2(e2, e3);
            sd[nt][0] = e0; sd[nt][1] = e1; sd[nt][2] = e2; sd[nt][3] = e3;
        }

        // ---- convert accumulator layout -> A-fragment layout via shuffles ----
        // A(row grp, col tg)  = D(grp, tg)  : lane (t&~3)|(tg>>1), reg parity tg&1
        // A(row grp, col tg+4)= D(grp, tg+4): lane src0+2, same parity
        unsigned ea[4][4];
        #pragma unroll
        for (int nt = 0; nt < 4; ++nt) {
            float x0 = __shfl_sync(FULLMASK, sd[nt][0], src0);
            float x1 = __shfl_sync(FULLMASK, sd[nt][1], src0);
            float x2 = __shfl_sync(FULLMASK, sd[nt][2], src0);
            float x3 = __shfl_sync(FULLMASK, sd[nt][3], src0);
            float y0 = __shfl_sync(FULLMASK, sd[nt][0], src1);
            float y1 = __shfl_sync(FULLMASK, sd[nt][1], src1);
            float y2 = __shfl_sync(FULLMASK, sd[nt][2], src1);
            float y3 = __shfl_sync(FULLMASK, sd[nt][3], src1);
            ea[nt][0] = __float_as_uint(to_tf32(odd ? x1 : x0));
            ea[nt][1] = __float_as_uint(to_tf32(odd ? x3 : x2));
            ea[nt][2] = __float_as_uint(to_tf32(odd ? y1 : y0));
            ea[nt][3] = __float_as_uint(to_tf32(odd ? y3 : y2));
        }

        // ---- ctx partial: ctx(m16 x n64) += E(warp's 32 e-cols) . V ----
        const unsigned* Vu = (const unsigned*)Vs;
        #pragma unroll
        for (int nt = 0; nt < 4; ++nt) {
            int kr = ng * 32 + nt * 8;                        // value seq offset in tile
            #pragma unroll
            for (int ct = 0; ct < 8; ++ct) {
                unsigned b0 = Vu[(kr + tg)     * LDV + ct * 8 + grp];
                unsigned b1 = Vu[(kr + tg + 4) * LDV + ct * 8 + grp];
                mma_tf32(ctxa[ct], ea[nt], b0, b1);
            }
        }
        __syncthreads();   // all smem reads done before next iteration's stores
    }

    // ---- rowsum reduction: lanes (tg) -> per-warp; ng pairs via smem ----
    rsum_lo += __shfl_xor_sync(FULLMASK, rsum_lo, 1);
    rsum_lo += __shfl_xor_sync(FULLMASK, rsum_lo, 2);
    rsum_hi += __shfl_xor_sync(FULLMASK, rsum_hi, 1);
    rsum_hi += __shfl_xor_sync(FULLMASK, rsum_hi, 2);
    if (tg == 0) {
        s_sums[ng * TQ + row0] = rsum_lo;
        s_sums[ng * TQ + row1] = rsum_hi;
    }
    __syncthreads();
    if (tid < TQ) s_inv[tid] = 1.f / (s_sums[tid] + s_sums[TQ + tid] + 1e-8f);
    __syncthreads();

    // ---- ctx 2-way partial reduction (ng=0 stages, ng=1 adds + writes) ----
    float* ctxbuf = Ks;   // Ks dead after loop
    if (ng == 0) {
        #pragma unroll
        for (int ct = 0; ct < 8; ++ct) {
            int c = ct * 8 + 2 * tg;
            *(float2*)&ctxbuf[row0 * LDC + c] = make_float2(ctxa[ct][0], ctxa[ct][1]);
            *(float2*)&ctxbuf[row1 * LDC + c] = make_float2(ctxa[ct][2], ctxa[ct][3]);
        }
    }
    __syncthreads();
    if (ng == 1) {
        float ilo = s_inv[row0], ihi = s_inv[row1];
        #pragma unroll
        for (int ct = 0; ct < 8; ++ct) {
            int c = ct * 8 + 2 * tg;
            float2 p0 = *(float2*)&ctxbuf[row0 * LDC + c];
            float2 p1 = *(float2*)&ctxbuf[row1 * LDC + c];
            *(float2*)(Cb + (size_t)row0 * DK + c) =
                make_float2((p0.x + ctxa[ct][0]) * ilo, (p0.y + ctxa[ct][1]) * ilo);
            *(float2*)(Cb + (size_t)row1 * DK + c) =
                make_float2((p1.x + ctxa[ct][2]) * ihi, (p1.y + ctxa[ct][3]) * ihi);
        }
    }

    // ---- normalize attn strip in place (coalesced float4; mostly L2-hot) ----
    for (int ii = tid; ii < TQ * (SEQ / 4); ii += 256) {
        int r  = ii >> 9;                 // SEQ/4 = 512 float4 per row
        int c4 = (ii & 511) << 2;
        float inv = s_inv[r];
        float4 v = *(float4*)(Ab + (size_t)r * SEQ + c4);
        v.x *= inv; v.y *= inv; v.z *= inv; v.w *= inv;
        *(float4*)(Ab + (size_t)r * SEQ + c4) = v;
    }
}

extern "C" void kernel_launch(void* const* d_in, const int* in_sizes, int n_in,
                              void* d_out, int out_size)
{
    const float* Q = (const float*)d_in[0];
    const float* K = (const float*)d_in[1];
    const float* V = (const float*)d_in[2];
    const float* M = (const float*)d_in[3];

    float* ctx  = (float*)d_out;                                    // B*H*S*DK
    float* attn = (float*)d_out + (size_t)BATCH * HEADS * SEQ * DK; // B*H*S*S

    dim3 grid(SEQ / TQ, HEADS, BATCH);
    attn_kernel<<<grid, 256>>>(Q, K, V, M, ctx, attn);
}

// round 12
// speedup vs baseline: 1.5924x; 1.5924x over previous
#include <cuda_runtime.h>

#define BATCH 4
#define HEADS 12
#define SEQ   2048
#define DK    64
#define TQ    64
#define TK    64
#define NT    (SEQ / TK)
#define LDK   68   // K smem pitch: banks 4*grp+tg for b-frags, conflict-free; 272B row, 16B aligned
#define LDV   72   // V smem pitch: banks 8*tg+grp, conflict-free; 288B row, 16B aligned
#define LDC   66   // ctx reduce buffer pitch
#define FULLMASK 0xffffffffu

__device__ __forceinline__ float to_tf32(float x) {
    asm("cvt.rna.tf32.f32 %0, %0;" : "+f"(x));
    return x;
}
__device__ __forceinline__ unsigned ldcvt(const float* p) {
    return __float_as_uint(to_tf32(*p));
}

// D = A(16x8 tf32, row) * B(8x8 tf32, col) + D, fp32 accum
__device__ __forceinline__ void mma_tf32(float d[4], const unsigned a[4],
                                         unsigned b0, unsigned b1) {
    asm volatile(
        "mma.sync.aligned.m16n8k8.row.col.f32.tf32.tf32.f32 "
        "{%0,%1,%2,%3}, {%4,%5,%6,%7}, {%8,%9}, {%0,%1,%2,%3};"
        : "+f"(d[0]), "+f"(d[1]), "+f"(d[2]), "+f"(d[3])
        : "r"(a[0]), "r"(a[1]), "r"(a[2]), "r"(a[3]), "r"(b0), "r"(b1));
}

__device__ __forceinline__ void cp16(float* dst_smem, const float* src) {
    unsigned d = (unsigned)__cvta_generic_to_shared(dst_smem);
    asm volatile("cp.async.cg.shared.global [%0], [%1], 16;" :: "r"(d), "l"(src));
}

__global__ void __launch_bounds__(256, 2)
attn_kernel(const float* __restrict__ Q, const float* __restrict__ K,
            const float* __restrict__ V, const float* __restrict__ M,
            float* __restrict__ ctx_out, float* __restrict__ attn_out)
{
    extern __shared__ float dynsm[];
    float* K0 = dynsm;                          // [TK*LDK]
    float* K1 = dynsm + TK * LDK;
    float* V0 = dynsm + 2 * TK * LDK;           // [TK*LDV]
    float* V1 = dynsm + 2 * TK * LDK + TK * LDV;
    __shared__ float s_sums[2 * TQ];
    __shared__ float s_inv[TQ];

    const int qt = blockIdx.x, h = blockIdx.y, b = blockIdx.z;
    const int tid  = threadIdx.x;
    const int warp = tid >> 5;
    const int lane = tid & 31;
    const int mg = warp >> 1;          // 4 m-groups: rows mg*16 .. +15
    const int ng = warp & 1;           // 2 n-groups: score cols ng*32 .. +31 per tile
    const int grp = lane >> 2;         // 0..7
    const int tg  = lane & 3;          // 0..3

    const size_t bh = (size_t)b * HEADS + h;
    const float* Qb = Q + (bh * SEQ + (size_t)qt * TQ) * DK;
    const float* Kb = K + bh * SEQ * DK;
    const float* Vb = V + bh * SEQ * DK;
    const float* Mb = M + ((size_t)b * SEQ + (size_t)qt * TQ) * SEQ;
    float* Ab = attn_out + (bh * SEQ + (size_t)qt * TQ) * SEQ;
    float* Cb = ctx_out  + (bh * SEQ + (size_t)qt * TQ) * DK;

    const int row0 = mg * 16 + grp;
    const int row1 = row0 + 8;

    // ---- prologue: stage Q (raw fp32) into K0, build tf32 a-fragments ----
    for (int i = tid; i < TQ * 16; i += 256) {
        int r = i >> 4, c = (i & 15) << 2;
        *(float4*)&K0[r * LDK + c] = *(const float4*)(Qb + (size_t)r * DK + c);
    }
    __syncthreads();

    unsigned qa[8][4];
    #pragma unroll
    for (int kk = 0; kk < 8; ++kk) {
        qa[kk][0] = ldcvt(&K0[row0 * LDK + kk * 8 + tg]);
        qa[kk][1] = ldcvt(&K0[row1 * LDK + kk * 8 + tg]);
        qa[kk][2] = ldcvt(&K0[row0 * LDK + kk * 8 + tg + 4]);
        qa[kk][3] = ldcvt(&K0[row1 * LDK + kk * 8 + tg + 4]);
    }
    __syncthreads();

    // ---- issue tile 0 into buffer 0 ----
    #pragma unroll
    for (int it = 0; it < 4; ++it) {
        int c = tid + it * 256;            // 1024 chunks of 16B per tile
        int r = c >> 4, off = (c & 15) << 2;
        cp16(K0 + r * LDK + off, Kb + (size_t)r * DK + off);
        cp16(V0 + r * LDV + off, Vb + (size_t)r * DK + off);
    }
    asm volatile("cp.async.commit_group;");

    float ctxa[8][4];
    #pragma unroll
    for (int i = 0; i < 8; ++i)
        #pragma unroll
        for (int j = 0; j < 4; ++j) ctxa[i][j] = 0.f;

    float rsum_lo = 0.f, rsum_hi = 0.f;

    const int src0 = (lane & ~3) | (tg >> 1);
    const int src1 = src0 + 2;
    const bool odd = (tg & 1) != 0;

    for (int kt = 0; kt < NT; ++kt) {
        float* Ks = (kt & 1) ? K1 : K0;
        float* Vs = (kt & 1) ? V1 : V0;

        // ---- issue next tile into alternate buffer (safe: bottom sync of kt-1 done) ----
        if (kt + 1 < NT) {
            float* Kn = (kt & 1) ? K0 : K1;
            float* Vn = (kt & 1) ? V0 : V1;
            const float* kg = Kb + (size_t)(kt + 1) * TK * DK;
            const float* vg = Vb + (size_t)(kt + 1) * TK * DK;
            #pragma unroll
            for (int it = 0; it < 4; ++it) {
                int c = tid + it * 256;
                int r = c >> 4, off = (c & 15) << 2;
                cp16(Kn + r * LDK + off, kg + (size_t)r * DK + off);
                cp16(Vn + r * LDV + off, vg + (size_t)r * DK + off);
            }
            asm volatile("cp.async.commit_group;");
            asm volatile("cp.async.wait_group 1;");   // drain group kt (leave kt+1 in flight)
        } else {
            asm volatile("cp.async.wait_group 0;");
        }
        __syncthreads();   // current buffers visible to all threads

        // ---- prefetch mask fragments (consumed after score MMAs) ----
        float2 mk0[4], mk1[4];
        #pragma unroll
        for (int nt = 0; nt < 4; ++nt) {
            int col = kt * TK + ng * 32 + nt * 8 + 2 * tg;
            mk0[nt] = *(const float2*)(Mb + (size_t)row0 * SEQ + col);
            mk1[nt] = *(const float2*)(Mb + (size_t)row1 * SEQ + col);
        }

        // ---- scores: D(m16 x n32) = Q . K^T ----
        float sd[4][4];
        #pragma unroll
        for (int nt = 0; nt < 4; ++nt)
            #pragma unroll
            for (int j = 0; j < 4; ++j) sd[nt][j] = 0.f;

        #pragma unroll
        for (int kk = 0; kk < 8; ++kk) {
            #pragma unroll
            for (int nt = 0; nt < 4; ++nt) {
                int nr = ng * 32 + nt * 8 + grp;
                unsigned b0 = ldcvt(&Ks[nr * LDK + kk * 8 + tg]);
                unsigned b1 = ldcvt(&Ks[nr * LDK + kk * 8 + tg + 4]);
                mma_tf32(sd[nt], qa[kk], b0, b1);
            }
        }

        // ---- e = exp(s/8)*mask; rowsum; write unnormalized attn ----
        #pragma unroll
        for (int nt = 0; nt < 4; ++nt) {
            int col = kt * TK + ng * 32 + nt * 8 + 2 * tg;
            float e0 = __expf(sd[nt][0] * 0.125f) * mk0[nt].x;
            float e1 = __expf(sd[nt][1] * 0.125f) * mk0[nt].y;
            float e2 = __expf(sd[nt][2] * 0.125f) * mk1[nt].x;
            float e3 = __expf(sd[nt][3] * 0.125f) * mk1[nt].y;
            rsum_lo += e0 + e1;
            rsum_hi += e2 + e3;
            *(float2*)(Ab + (size_t)row0 * SEQ + col) = make_float2(e0, e1);
            *(float2*)(Ab + (size_t)row1 * SEQ + col) = make_float2(e2, e3);
            sd[nt][0] = e0; sd[nt][1] = e1; sd[nt][2] = e2; sd[nt][3] = e3;
        }

        // ---- D-layout -> A-layout via shuffles ----
        unsigned ea[4][4];
        #pragma unroll
        for (int nt = 0; nt < 4; ++nt) {
            float x0 = __shfl_sync(FULLMASK, sd[nt][0], src0);
            float x1 = __shfl_sync(FULLMASK, sd[nt][1], src0);
            float x2 = __shfl_sync(FULLMASK, sd[nt][2], src0);
            float x3 = __shfl_sync(FULLMASK, sd[nt][3], src0);
            float y0 = __shfl_sync(FULLMASK, sd[nt][0], src1);
            float y1 = __shfl_sync(FULLMASK, sd[nt][1], src1);
            float y2 = __shfl_sync(FULLMASK, sd[nt][2], src1);
            float y3 = __shfl_sync(FULLMASK, sd[nt][3], src1);
            ea[nt][0] = __float_as_uint(to_tf32(odd ? x1 : x0));
            ea[nt][1] = __float_as_uint(to_tf32(odd ? x3 : x2));
            ea[nt][2] = __float_as_uint(to_tf32(odd ? y1 : y0));
            ea[nt][3] = __float_as_uint(to_tf32(odd ? y3 : y2));
        }

        // ---- ctx partial: ctx(m16 x n64) += E . V ----
        #pragma unroll
        for (int nt = 0; nt < 4; ++nt) {
            int kr = ng * 32 + nt * 8;
            #pragma unroll
            for (int ct = 0; ct < 8; ++ct) {
                unsigned b0 = ldcvt(&Vs[(kr + tg)     * LDV + ct * 8 + grp]);
                unsigned b1 = ldcvt(&Vs[(kr + tg + 4) * LDV + ct * 8 + grp]);
                mma_tf32(ctxa[ct], ea[nt], b0, b1);
            }
        }
        __syncthreads();   // all reads of current buffers done (next iter overwrites)
    }

    // ---- rowsum reduction ----
    rsum_lo += __shfl_xor_sync(FULLMASK, rsum_lo, 1);
    rsum_lo += __shfl_xor_sync(FULLMASK, rsum_lo, 2);
    rsum_hi += __shfl_xor_sync(FULLMASK, rsum_hi, 1);
    rsum_hi += __shfl_xor_sync(FULLMASK, rsum_hi, 2);
    if (tg == 0) {
        s_sums[ng * TQ + row0] = rsum_lo;
        s_sums[ng * TQ + row1] = rsum_hi;
    }
    __syncthreads();
    if (tid < TQ) s_inv[tid] = 1.f / (s_sums[tid] + s_sums[TQ + tid] + 1e-8f);
    __syncthreads();

    // ---- ctx 2-way partial reduction (ng=0 stages, ng=1 adds + writes) ----
    float* ctxbuf = dynsm;   // tile buffers dead
    if (ng == 0) {
        #pragma unroll
        for (int ct = 0; ct < 8; ++ct) {
            int c = ct * 8 + 2 * tg;
            *(float2*)&ctxbuf[row0 * LDC + c] = make_float2(ctxa[ct][0], ctxa[ct][1]);
            *(float2*)&ctxbuf[row1 * LDC + c] = make_float2(ctxa[ct][2], ctxa[ct][3]);
        }
    }
    __syncthreads();
    if (ng == 1) {
        float ilo = s_inv[row0], ihi = s_inv[row1];
        #pragma unroll
        for (int ct = 0; ct < 8; ++ct) {
            int c = ct * 8 + 2 * tg;
            float2 p0 = *(float2*)&ctxbuf[row0 * LDC + c];
            float2 p1 = *(float2*)&ctxbuf[row1 * LDC + c];
            *(float2*)(Cb + (size_t)row0 * DK + c) =
                make_float2((p0.x + ctxa[ct][0]) * ilo, (p0.y + ctxa[ct][1]) * ilo);
            *(float2*)(Cb + (size_t)row1 * DK + c) =
                make_float2((p1.x + ctxa[ct][2]) * ihi, (p1.y + ctxa[ct][3]) * ihi);
        }
    }

    // ---- normalize attn strip in place (coalesced float4) ----
    for (int ii = tid; ii < TQ * (SEQ / 4); ii += 256) {
        int r  = ii >> 9;
        int c4 = (ii & 511) << 2;
        float inv = s_inv[r];
        float4 v = *(float4*)(Ab + (size_t)r * SEQ + c4);
        v.x *= inv; v.y *= inv; v.z *= inv; v.w *= inv;
        *(float4*)(Ab + (size_t)r * SEQ + c4) = v;
    }
}

extern "C" void kernel_launch(void* const* d_in, const int* in_sizes, int n_in,
                              void* d_out, int out_size)
{
    const float* Q = (const float*)d_in[0];
    const float* K = (const float*)d_in[1];
    const float* V = (const float*)d_in[2];
    const float* M = (const float*)d_in[3];

    float* ctx  = (float*)d_out;                                    // B*H*S*DK
    float* attn = (float*)d_out + (size_t)BATCH * HEADS * SEQ * DK; // B*H*S*S

    const size_t smem = (size_t)(2 * TK * LDK + 2 * TK * LDV) * sizeof(float); // 71680 B
    cudaFuncSetAttribute(attn_kernel, cudaFuncAttributeMaxDynamicSharedMemorySize, (int)smem);

    dim3 grid(SEQ / TQ, HEADS, BATCH);
    attn_kernel<<<grid, 256, smem>>>(Q, K, V, M, ctx, attn);
}

// round 14
// speedup vs baseline: 1.7501x; 1.0990x over previous
#include <cuda_runtime.h>

#define BATCH 4
#define HEADS 12
#define SEQ   2048
#define DK    64
#define TQ    64
#define TK    64
#define NT    (SEQ / TK)
#define LDK   68   // K smem pitch: b-frag banks 4*grp+tg+8kk, conflict-free
#define LDV   72   // V smem pitch: b-frag banks 8*tg+grp+8ct, conflict-free
#define LDM   68   // mask/attn staging pitch (float2 frag access <=2-way conflict)
#define LDC   66   // ctx reduce buffer pitch
#define FULLMASK 0xffffffffu

__device__ __forceinline__ float to_tf32(float x) {
    asm("cvt.rna.tf32.f32 %0, %0;" : "+f"(x));
    return x;
}
__device__ __forceinline__ unsigned ldcvt(const float* p) {
    return __float_as_uint(to_tf32(*p));
}

// D = A(16x8 tf32, row) * B(8x8 tf32, col) + D, fp32 accum
__device__ __forceinline__ void mma_tf32(float d[4], const unsigned a[4],
                                         unsigned b0, unsigned b1) {
    asm volatile(
        "mma.sync.aligned.m16n8k8.row.col.f32.tf32.tf32.f32 "
        "{%0,%1,%2,%3}, {%4,%5,%6,%7}, {%8,%9}, {%0,%1,%2,%3};"
        : "+f"(d[0]), "+f"(d[1]), "+f"(d[2]), "+f"(d[3])
        : "r"(a[0]), "r"(a[1]), "r"(a[2]), "r"(a[3]), "r"(b0), "r"(b1));
}

__device__ __forceinline__ void cp16(float* dst_smem, const float* src) {
    unsigned d = (unsigned)__cvta_generic_to_shared(dst_smem);
    asm volatile("cp.async.cg.shared.global [%0], [%1], 16;" :: "r"(d), "l"(src));
}

__global__ void __launch_bounds__(256, 2)
attn_kernel(const float* __restrict__ Q, const float* __restrict__ K,
            const float* __restrict__ V, const float* __restrict__ M,
            float* __restrict__ ctx_out, float* __restrict__ attn_out)
{
    extern __shared__ float dynsm[];
    float* K0 = dynsm;                  // [TK*LDK]
    float* K1 = K0 + TK * LDK;
    float* V0 = K1 + TK * LDK;          // [TK*LDV]
    float* V1 = V0 + TK * LDV;
    float* M0 = V1 + TK * LDV;          // [TQ*LDM] mask tile / attn staging
    float* M1 = M0 + TQ * LDM;
    __shared__ float s_sums[2 * TQ];
    __shared__ float s_inv[TQ];

    const int qt = blockIdx.x, h = blockIdx.y, b = blockIdx.z;
    const int tid  = threadIdx.x;
    const int lane = tid & 31;
    const int warp = tid >> 5;
    const int mg = warp >> 1;          // rows mg*16 .. +15
    const int ng = warp & 1;           // score cols ng*32 .. +31 within tile
    const int grp = lane >> 2;         // 0..7
    const int tg  = lane & 3;          // 0..3

    const size_t bh = (size_t)b * HEADS + h;
    const float* Qb = Q + (bh * SEQ + (size_t)qt * TQ) * DK;
    const float* Kb = K + bh * SEQ * DK;
    const float* Vb = V + bh * SEQ * DK;
    const float* Mb = M + ((size_t)b * SEQ + (size_t)qt * TQ) * SEQ;
    float* Ab = attn_out + (bh * SEQ + (size_t)qt * TQ) * SEQ;
    float* Cb = ctx_out  + (bh * SEQ + (size_t)qt * TQ) * DK;

    const int row0 = mg * 16 + grp;
    const int row1 = row0 + 8;
    const int col_base = ng * 32 + 2 * tg;

    // ---- prologue: stage Q (raw) into K0, build tf32 a-fragments ----
    for (int i = tid; i < TQ * 16; i += 256) {
        int r = i >> 4, c = (i & 15) << 2;
        *(float4*)&K0[r * LDK + c] = *(const float4*)(Qb + (size_t)r * DK + c);
    }
    __syncthreads();

    unsigned qa[8][4];
    #pragma unroll
    for (int kk = 0; kk < 8; ++kk) {
        qa[kk][0] = ldcvt(&K0[row0 * LDK + kk * 8 + tg]);
        qa[kk][1] = ldcvt(&K0[row1 * LDK + kk * 8 + tg]);
        qa[kk][2] = ldcvt(&K0[row0 * LDK + kk * 8 + tg + 4]);
        qa[kk][3] = ldcvt(&K0[row1 * LDK + kk * 8 + tg + 4]);
    }
    __syncthreads();

    const int src0 = (lane & ~3) | (tg >> 1);
    const int src1 = src0 + 2;
    const bool odd = (tg & 1) != 0;

    // ======================= PASS 1: rowsums only =======================
    #pragma unroll
    for (int it = 0; it < 4; ++it) {
        int c = tid + it * 256;
        int r = c >> 4, off = (c & 15) << 2;
        cp16(K0 + r * LDK + off, Kb + (size_t)r * DK + off);
        cp16(M0 + r * LDM + off, Mb + (size_t)r * SEQ + off);
    }
    asm volatile("cp.async.commit_group;");

    float rsum_lo = 0.f, rsum_hi = 0.f;

    for (int kt = 0; kt < NT; ++kt) {
        float* Ks = (kt & 1) ? K1 : K0;
        float* Ms = (kt & 1) ? M1 : M0;

        if (kt + 1 < NT) {
            float* Kn = (kt & 1) ? K0 : K1;
            float* Mn = (kt & 1) ? M0 : M1;
            const float* kg = Kb + (size_t)(kt + 1) * TK * DK;
            const float* mgp = Mb + (kt + 1) * TK;
            #pragma unroll
            for (int it = 0; it < 4; ++it) {
                int c = tid + it * 256;
                int r = c >> 4, off = (c & 15) << 2;
                cp16(Kn + r * LDK + off, kg + (size_t)r * DK + off);
                cp16(Mn + r * LDM + off, mgp + (size_t)r * SEQ + off);
            }
            asm volatile("cp.async.commit_group;");
            asm volatile("cp.async.wait_group 1;");
        } else {
            asm volatile("cp.async.wait_group 0;");
        }
        __syncthreads();

        float sd[4][4];
        #pragma unroll
        for (int nt = 0; nt < 4; ++nt)
            #pragma unroll
            for (int j = 0; j < 4; ++j) sd[nt][j] = 0.f;

        #pragma unroll
        for (int kk = 0; kk < 8; ++kk) {
            #pragma unroll
            for (int nt = 0; nt < 4; ++nt) {
                int nr = ng * 32 + nt * 8 + grp;
                unsigned b0 = ldcvt(&Ks[nr * LDK + kk * 8 + tg]);
                unsigned b1 = ldcvt(&Ks[nr * LDK + kk * 8 + tg + 4]);
                mma_tf32(sd[nt], qa[kk], b0, b1);
            }
        }

        #pragma unroll
        for (int nt = 0; nt < 4; ++nt) {
            int cs = col_base + nt * 8;
            float2 m0 = *(const float2*)&Ms[row0 * LDM + cs];
            float2 m1 = *(const float2*)&Ms[row1 * LDM + cs];
            rsum_lo += __expf(sd[nt][0] * 0.125f) * m0.x
                     + __expf(sd[nt][1] * 0.125f) * m0.y;
            rsum_hi += __expf(sd[nt][2] * 0.125f) * m1.x
                     + __expf(sd[nt][3] * 0.125f) * m1.y;
        }
        __syncthreads();
    }

    // ---- rowsums -> inverse denominators ----
    rsum_lo += __shfl_xor_sync(FULLMASK, rsum_lo, 1);
    rsum_lo += __shfl_xor_sync(FULLMASK, rsum_lo, 2);
    rsum_hi += __shfl_xor_sync(FULLMASK, rsum_hi, 1);
    rsum_hi += __shfl_xor_sync(FULLMASK, rsum_hi, 2);
    if (tg == 0) {
        s_sums[ng * TQ + row0] = rsum_lo;
        s_sums[ng * TQ + row1] = rsum_hi;
    }
    __syncthreads();
    if (tid < TQ) s_inv[tid] = 1.f / (s_sums[tid] + s_sums[TQ + tid] + 1e-8f);
    __syncthreads();

    const float ilo = s_inv[row0];
    const float ihi = s_inv[row1];

    // ================= PASS 2: normalized attn + context =================
    #pragma unroll
    for (int it = 0; it < 4; ++it) {
        int c = tid + it * 256;
        int r = c >> 4, off = (c & 15) << 2;
        cp16(K0 + r * LDK + off, Kb + (size_t)r * DK + off);
        cp16(V0 + r * LDV + off, Vb + (size_t)r * DK + off);
        cp16(M0 + r * LDM + off, Mb + (size_t)r * SEQ + off);
    }
    asm volatile("cp.async.commit_group;");

    float ctxa[8][4];
    #pragma unroll
    for (int i = 0; i < 8; ++i)
        #pragma unroll
        for (int j = 0; j < 4; ++j) ctxa[i][j] = 0.f;

    for (int kt = 0; kt < NT; ++kt) {
        float* Ks = (kt & 1) ? K1 : K0;
        float* Vs = (kt & 1) ? V1 : V0;
        float* Ms = (kt & 1) ? M1 : M0;

        if (kt + 1 < NT) {
            float* Kn = (kt & 1) ? K0 : K1;
            float* Vn = (kt & 1) ? V0 : V1;
            float* Mn = (kt & 1) ? M0 : M1;
            const float* kg = Kb + (size_t)(kt + 1) * TK * DK;
            const float* vg = Vb + (size_t)(kt + 1) * TK * DK;
            const float* mgp = Mb + (kt + 1) * TK;
            #pragma unroll
            for (int it = 0; it < 4; ++it) {
                int c = tid + it * 256;
                int r = c >> 4, off = (c & 15) << 2;
                cp16(Kn + r * LDK + off, kg + (size_t)r * DK + off);
                cp16(Vn + r * LDV + off, vg + (size_t)r * DK + off);
                cp16(Mn + r * LDM + off, mgp + (size_t)r * SEQ + off);
            }
            asm volatile("cp.async.commit_group;");
            asm volatile("cp.async.wait_group 1;");
        } else {
            asm volatile("cp.async.wait_group 0;");
        }
        __syncthreads();

        // ---- scores (recompute; bit-identical to pass 1) ----
        float sd[4][4];
        #pragma unroll
        for (int nt = 0; nt < 4; ++nt)
            #pragma unroll
            for (int j = 0; j < 4; ++j) sd[nt][j] = 0.f;

        #pragma unroll
        for (int kk = 0; kk < 8; ++kk) {
            #pragma unroll
            for (int nt = 0; nt < 4; ++nt) {
                int nr = ng * 32 + nt * 8 + grp;
                unsigned b0 = ldcvt(&Ks[nr * LDK + kk * 8 + tg]);
                unsigned b1 = ldcvt(&Ks[nr * LDK + kk * 8 + tg + 4]);
                mma_tf32(sd[nt], qa[kk], b0, b1);
            }
        }

        // ---- e_norm = exp(s/8)*mask*inv ; stage into Ms (lane-private cells) ----
        #pragma unroll
        for (int nt = 0; nt < 4; ++nt) {
            int cs = col_base + nt * 8;
            float2 m0 = *(const float2*)&Ms[row0 * LDM + cs];
            float2 m1 = *(const float2*)&Ms[row1 * LDM + cs];
            float e0 = __expf(sd[nt][0] * 0.125f) * m0.x * ilo;
            float e1 = __expf(sd[nt][1] * 0.125f) * m0.y * ilo;
            float e2 = __expf(sd[nt][2] * 0.125f) * m1.x * ihi;
            float e3 = __expf(sd[nt][3] * 0.125f) * m1.y * ihi;
            *(float2*)&Ms[row0 * LDM + cs] = make_float2(e0, e1);
            *(float2*)&Ms[row1 * LDM + cs] = make_float2(e2, e3);
            sd[nt][0] = e0; sd[nt][1] = e1; sd[nt][2] = e2; sd[nt][3] = e3;
        }

        // ---- D-layout -> A-layout via shuffles (on normalized e) ----
        unsigned ea[4][4];
        #pragma unroll
        for (int nt = 0; nt < 4; ++nt) {
            float x0 = __shfl_sync(FULLMASK, sd[nt][0], src0);
            float x1 = __shfl_sync(FULLMASK, sd[nt][1], src0);
            float x2 = __shfl_sync(FULLMASK, sd[nt][2], src0);
            float x3 = __shfl_sync(FULLMASK, sd[nt][3], src0);
            float y0 = __shfl_sync(FULLMASK, sd[nt][0], src1);
            float y1 = __shfl_sync(FULLMASK, sd[nt][1], src1);
            float y2 = __shfl_sync(FULLMASK, sd[nt][2], src1);
            float y3 = __shfl_sync(FULLMASK, sd[nt][3], src1);
            ea[nt][0] = __float_as_uint(to_tf32(odd ? x1 : x0));
            ea[nt][1] = __float_as_uint(to_tf32(odd ? x3 : x2));
            ea[nt][2] = __float_as_uint(to_tf32(odd ? y1 : y0));
            ea[nt][3] = __float_as_uint(to_tf32(odd ? y3 : y2));
        }

        // ---- ctx += E_norm . V ----
        #pragma unroll
        for (int nt = 0; nt < 4; ++nt) {
            int kr = ng * 32 + nt * 8;
            #pragma unroll
            for (int ct = 0; ct < 8; ++ct) {
                unsigned b0 = ldcvt(&Vs[(kr + tg)     * LDV + ct * 8 + grp]);
                unsigned b1 = ldcvt(&Vs[(kr + tg + 4) * LDV + ct * 8 + grp]);
                mma_tf32(ctxa[ct], ea[nt], b0, b1);
            }
        }
        __syncthreads();   // all warps' staged e visible; tile reads done

        // ---- coalesced streaming write of normalized attn tile ----
        {
            float* ag = Ab + kt * TK;
            #pragma unroll
            for (int it = 0; it < 4; ++it) {
                int idx = tid + it * 256;
                int r = idx >> 4, c4 = (idx & 15) << 2;
                float4 v = *(float4*)&Ms[r * LDM + c4];
                __stcs((float4*)(ag + (size_t)r * SEQ + c4), v);
            }
        }
        __syncthreads();   // staging reads done before next cp.async overwrites
    }

    // ---- ctx 2-way partial reduction (ng=0 stages, ng=1 adds + writes) ----
    float* ctxbuf = dynsm;   // tile buffers dead
    if (ng == 0) {
        #pragma unroll
        for (int ct = 0; ct < 8; ++ct) {
            int c = ct * 8 + 2 * tg;
            *(float2*)&ctxbuf[row0 * LDC + c] = make_float2(ctxa[ct][0], ctxa[ct][1]);
            *(float2*)&ctxbuf[row1 * LDC + c] = make_float2(ctxa[ct][2], ctxa[ct][3]);
        }
    }
    __syncthreads();
    if (ng == 1) {
        #pragma unroll
        for (int ct = 0; ct < 8; ++ct) {
            int c = ct * 8 + 2 * tg;
            float2 p0 = *(float2*)&ctxbuf[row0 * LDC + c];
            float2 p1 = *(float2*)&ctxbuf[row1 * LDC + c];
            *(float2*)(Cb + (size_t)row0 * DK + c) =
                make_float2(p0.x + ctxa[ct][0], p0.y + ctxa[ct][1]);
            *(float2*)(Cb + (size_t)row1 * DK + c) =
                make_float2(p1.x + ctxa[ct][2], p1.y + ctxa[ct][3]);
        }
    }
}

extern "C" void kernel_launch(void* const* d_in, const int* in_sizes, int n_in,
                              void* d_out, int out_size)
{
    const float* Q = (const float*)d_in[0];
    const float* K = (const float*)d_in[1];
    const float* V = (const float*)d_in[2];
    const float* M = (const float*)d_in[3];

    float* ctx  = (float*)d_out;                                    // B*H*S*DK
    float* attn = (float*)d_out + (size_t)BATCH * HEADS * SEQ * DK; // B*H*S*S

    const size_t smem = (size_t)(2 * TK * LDK + 2 * TK * LDV + 2 * TQ * LDM)
                        * sizeof(float);                            // 106496 B
    cudaFuncSetAttribute(attn_kernel, cudaFuncAttributeMaxDynamicSharedMemorySize, (int)smem);

    dim3 grid(SEQ / TQ, HEADS, BATCH);
    attn_kernel<<<grid, 256, smem>>>(Q, K, V, M, ctx, attn);
}

// round 15
// speedup vs baseline: 1.9390x; 1.1079x over previous
#include <cuda_runtime.h>

#define BATCH 4
#define HEADS 12
#define SEQ   2048
#define DK    64
#define TQ    64
#define TK    64
#define NT    (SEQ / TK)
#define LDK   68   // K smem pitch: b-frag banks 4*grp+tg+8kk, conflict-free
#define LDV   72   // V smem pitch: b-frag banks 8*tg+grp+8ct, conflict-free
#define LDM   68   // mask/attn staging pitch
#define LDC   66   // ctx reduce buffer pitch
#define FULLMASK 0xffffffffu
#define KV_ELEMS (BATCH * HEADS * SEQ * DK)   // 6,291,456 floats = 25.2 MB

// tf32-pre-rounded K and V (scratch via __device__ globals -- allocation-free)
__device__ float g_Kt[KV_ELEMS];
__device__ float g_Vt[KV_ELEMS];

__device__ __forceinline__ float to_tf32(float x) {
    asm("cvt.rna.tf32.f32 %0, %0;" : "+f"(x));
    return x;
}
__device__ __forceinline__ unsigned ldcvt(const float* p) {
    return __float_as_uint(to_tf32(*p));
}
__device__ __forceinline__ unsigned ldu(const float* p) {
    return __float_as_uint(*p);
}

// D = A(16x8 tf32, row) * B(8x8 tf32, col) + D, fp32 accum
__device__ __forceinline__ void mma_tf32(float d[4], const unsigned a[4],
                                         unsigned b0, unsigned b1) {
    asm volatile(
        "mma.sync.aligned.m16n8k8.row.col.f32.tf32.tf32.f32 "
        "{%0,%1,%2,%3}, {%4,%5,%6,%7}, {%8,%9}, {%0,%1,%2,%3};"
        : "+f"(d[0]), "+f"(d[1]), "+f"(d[2]), "+f"(d[3])
        : "r"(a[0]), "r"(a[1]), "r"(a[2]), "r"(a[3]), "r"(b0), "r"(b1));
}

__device__ __forceinline__ void cp16(float* dst_smem, const float* src) {
    unsigned d = (unsigned)__cvta_generic_to_shared(dst_smem);
    asm volatile("cp.async.cg.shared.global [%0], [%1], 16;" :: "r"(d), "l"(src));
}

// ---- prep: round K,V to tf32 once (memory-bound, ~20us) ----
__global__ void __launch_bounds__(256)
prep_kernel(const float* __restrict__ K, const float* __restrict__ V)
{
    int i = blockIdx.x * 256 + threadIdx.x;          // one float4 per thread
    const int N4 = KV_ELEMS / 4;
    if (i < N4) {
        float4 v = *(const float4*)(K + (size_t)i * 4);
        v.x = to_tf32(v.x); v.y = to_tf32(v.y); v.z = to_tf32(v.z); v.w = to_tf32(v.w);
        *(float4*)(g_Kt + (size_t)i * 4) = v;
    } else {
        int j = i - N4;
        float4 v = *(const float4*)(V + (size_t)j * 4);
        v.x = to_tf32(v.x); v.y = to_tf32(v.y); v.z = to_tf32(v.z); v.w = to_tf32(v.w);
        *(float4*)(g_Vt + (size_t)j * 4) = v;
    }
}

__global__ void __launch_bounds__(256, 2)
attn_kernel(const float* __restrict__ Q, const float* __restrict__ M,
            float* __restrict__ ctx_out, float* __restrict__ attn_out)
{
    extern __shared__ float dynsm[];
    float* K0 = dynsm;                  // [TK*LDK]
    float* K1 = K0 + TK * LDK;
    float* V0 = K1 + TK * LDK;          // [TK*LDV]
    float* V1 = V0 + TK * LDV;
    float* M0 = V1 + TK * LDV;          // [TQ*LDM] mask tile / attn staging
    float* M1 = M0 + TQ * LDM;
    __shared__ float s_sums[2 * TQ];
    __shared__ float s_inv[TQ];

    const int qt = blockIdx.x, h = blockIdx.y, b = blockIdx.z;
    const int tid  = threadIdx.x;
    const int lane = tid & 31;
    const int warp = tid >> 5;
    const int mg = warp >> 1;          // rows mg*16 .. +15
    const int ng = warp & 1;           // score cols ng*32 .. +31 within tile
    const int grp = lane >> 2;         // 0..7
    const int tg  = lane & 3;          // 0..3

    const size_t bh = (size_t)b * HEADS + h;
    const float* Qb = Q + (bh * SEQ + (size_t)qt * TQ) * DK;
    const float* Kb = g_Kt + bh * SEQ * DK;
    const float* Vb = g_Vt + bh * SEQ * DK;
    const float* Mb = M + ((size_t)b * SEQ + (size_t)qt * TQ) * SEQ;
    float* Ab = attn_out + (bh * SEQ + (size_t)qt * TQ) * SEQ;
    float* Cb = ctx_out  + (bh * SEQ + (size_t)qt * TQ) * DK;

    const int row0 = mg * 16 + grp;
    const int row1 = row0 + 8;
    const int col_base = ng * 32 + 2 * tg;

    // ---- prologue: stage Q (raw) into K0, build tf32 a-fragments ----
    for (int i = tid; i < TQ * 16; i += 256) {
        int r = i >> 4, c = (i & 15) << 2;
        *(float4*)&K0[r * LDK + c] = *(const float4*)(Qb + (size_t)r * DK + c);
    }
    __syncthreads();

    unsigned qa[8][4];
    #pragma unroll
    for (int kk = 0; kk < 8; ++kk) {
        qa[kk][0] = ldcvt(&K0[row0 * LDK + kk * 8 + tg]);
        qa[kk][1] = ldcvt(&K0[row1 * LDK + kk * 8 + tg]);
        qa[kk][2] = ldcvt(&K0[row0 * LDK + kk * 8 + tg + 4]);
        qa[kk][3] = ldcvt(&K0[row1 * LDK + kk * 8 + tg + 4]);
    }
    __syncthreads();

    const int src0 = (lane & ~3) | (tg >> 1);
    const int src1 = src0 + 2;
    const bool odd = (tg & 1) != 0;

    // ======================= PASS 1: rowsums only =======================
    #pragma unroll
    for (int it = 0; it < 4; ++it) {
        int c = tid + it * 256;
        int r = c >> 4, off = (c & 15) << 2;
        cp16(K0 + r * LDK + off, Kb + (size_t)r * DK + off);
        cp16(M0 + r * LDM + off, Mb + (size_t)r * SEQ + off);
    }
    asm volatile("cp.async.commit_group;");

    float rsum_lo = 0.f, rsum_hi = 0.f;

    for (int kt = 0; kt < NT; ++kt) {
        float* Ks = (kt & 1) ? K1 : K0;
        float* Ms = (kt & 1) ? M1 : M0;

        if (kt + 1 < NT) {
            float* Kn = (kt & 1) ? K0 : K1;
            float* Mn = (kt & 1) ? M0 : M1;
            const float* kg = Kb + (size_t)(kt + 1) * TK * DK;
            const float* mgp = Mb + (kt + 1) * TK;
            #pragma unroll
            for (int it = 0; it < 4; ++it) {
                int c = tid + it * 256;
                int r = c >> 4, off = (c & 15) << 2;
                cp16(Kn + r * LDK + off, kg + (size_t)r * DK + off);
                cp16(Mn + r * LDM + off, mgp + (size_t)r * SEQ + off);
            }
            asm volatile("cp.async.commit_group;");
            asm volatile("cp.async.wait_group 1;");
        } else {
            asm volatile("cp.async.wait_group 0;");
        }
        __syncthreads();

        float sd[4][4];
        #pragma unroll
        for (int nt = 0; nt < 4; ++nt)
            #pragma unroll
            for (int j = 0; j < 4; ++j) sd[nt][j] = 0.f;

        #pragma unroll
        for (int kk = 0; kk < 8; ++kk) {
            #pragma unroll
            for (int nt = 0; nt < 4; ++nt) {
                int nr = ng * 32 + nt * 8 + grp;
                unsigned b0 = ldu(&Ks[nr * LDK + kk * 8 + tg]);
                unsigned b1 = ldu(&Ks[nr * LDK + kk * 8 + tg + 4]);
                mma_tf32(sd[nt], qa[kk], b0, b1);
            }
        }

        #pragma unroll
        for (int nt = 0; nt < 4; ++nt) {
            int cs = col_base + nt * 8;
            float2 m0 = *(const float2*)&Ms[row0 * LDM + cs];
            float2 m1 = *(const float2*)&Ms[row1 * LDM + cs];
            rsum_lo += __expf(sd[nt][0] * 0.125f) * m0.x
                     + __expf(sd[nt][1] * 0.125f) * m0.y;
            rsum_hi += __expf(sd[nt][2] * 0.125f) * m1.x
                     + __expf(sd[nt][3] * 0.125f) * m1.y;
        }
        __syncthreads();
    }

    // ---- rowsums -> inverse denominators ----
    rsum_lo += __shfl_xor_sync(FULLMASK, rsum_lo, 1);
    rsum_lo += __shfl_xor_sync(FULLMASK, rsum_lo, 2);
    rsum_hi += __shfl_xor_sync(FULLMASK, rsum_hi, 1);
    rsum_hi += __shfl_xor_sync(FULLMASK, rsum_hi, 2);
    if (tg == 0) {
        s_sums[ng * TQ + row0] = rsum_lo;
        s_sums[ng * TQ + row1] = rsum_hi;
    }
    __syncthreads();
    if (tid < TQ) s_inv[tid] = 1.f / (s_sums[tid] + s_sums[TQ + tid] + 1e-8f);
    __syncthreads();

    const float ilo = s_inv[row0];
    const float ihi = s_inv[row1];

    // ================= PASS 2: normalized attn + context =================
    #pragma unroll
    for (int it = 0; it < 4; ++it) {
        int c = tid + it * 256;
        int r = c >> 4, off = (c & 15) << 2;
        cp16(K0 + r * LDK + off, Kb + (size_t)r * DK + off);
        cp16(V0 + r * LDV + off, Vb + (size_t)r * DK + off);
        cp16(M0 + r * LDM + off, Mb + (size_t)r * SEQ + off);
    }
    asm volatile("cp.async.commit_group;");

    float ctxa[8][4];
    #pragma unroll
    for (int i = 0; i < 8; ++i)
        #pragma unroll
        for (int j = 0; j < 4; ++j) ctxa[i][j] = 0.f;

    for (int kt = 0; kt < NT; ++kt) {
        float* Ks = (kt & 1) ? K1 : K0;
        float* Vs = (kt & 1) ? V1 : V0;
        float* Ms = (kt & 1) ? M1 : M0;

        if (kt + 1 < NT) {
            float* Kn = (kt & 1) ? K0 : K1;
            float* Vn = (kt & 1) ? V0 : V1;
            float* Mn = (kt & 1) ? M0 : M1;
            const float* kg = Kb + (size_t)(kt + 1) * TK * DK;
            const float* vg = Vb + (size_t)(kt + 1) * TK * DK;
            const float* mgp = Mb + (kt + 1) * TK;
            #pragma unroll
            for (int it = 0; it < 4; ++it) {
                int c = tid + it * 256;
                int r = c >> 4, off = (c & 15) << 2;
                cp16(Kn + r * LDK + off, kg + (size_t)r * DK + off);
                cp16(Vn + r * LDV + off, vg + (size_t)r * DK + off);
                cp16(Mn + r * LDM + off, mgp + (size_t)r * SEQ + off);
            }
            asm volatile("cp.async.commit_group;");
            asm volatile("cp.async.wait_group 1;");
        } else {
            asm volatile("cp.async.wait_group 0;");
        }
        __syncthreads();

        // ---- scores (recompute; bit-identical to pass 1) ----
        float sd[4][4];
        #pragma unroll
        for (int nt = 0; nt < 4; ++nt)
            #pragma unroll
            for (int j = 0; j < 4; ++j) sd[nt][j] = 0.f;

        #pragma unroll
        for (int kk = 0; kk < 8; ++kk) {
            #pragma unroll
            for (int nt = 0; nt < 4; ++nt) {
                int nr = ng * 32 + nt * 8 + grp;
                unsigned b0 = ldu(&Ks[nr * LDK + kk * 8 + tg]);
                unsigned b1 = ldu(&Ks[nr * LDK + kk * 8 + tg + 4]);
                mma_tf32(sd[nt], qa[kk], b0, b1);
            }
        }

        // ---- e_norm = exp(s/8)*mask*inv ; stage into Ms (lane-private cells) ----
        #pragma unroll
        for (int nt = 0; nt < 4; ++nt) {
            int cs = col_base + nt * 8;
            float2 m0 = *(const float2*)&Ms[row0 * LDM + cs];
            float2 m1 = *(const float2*)&Ms[row1 * LDM + cs];
            float e0 = __expf(sd[nt][0] * 0.125f) * m0.x * ilo;
            float e1 = __expf(sd[nt][1] * 0.125f) * m0.y * ilo;
            float e2 = __expf(sd[nt][2] * 0.125f) * m1.x * ihi;
            float e3 = __expf(sd[nt][3] * 0.125f) * m1.y * ihi;
            *(float2*)&Ms[row0 * LDM + cs] = make_float2(e0, e1);
            *(float2*)&Ms[row1 * LDM + cs] = make_float2(e2, e3);
            sd[nt][0] = e0; sd[nt][1] = e1; sd[nt][2] = e2; sd[nt][3] = e3;
        }

        // ---- D-layout -> A-layout via shuffles (on normalized e) ----
        unsigned ea[4][4];
        #pragma unroll
        for (int nt = 0; nt < 4; ++nt) {
            float x0 = __shfl_sync(FULLMASK, sd[nt][0], src0);
            float x1 = __shfl_sync(FULLMASK, sd[nt][1], src0);
            float x2 = __shfl_sync(FULLMASK, sd[nt][2], src0);
            float x3 = __shfl_sync(FULLMASK, sd[nt][3], src0);
            float y0 = __shfl_sync(FULLMASK, sd[nt][0], src1);
            float y1 = __shfl_sync(FULLMASK, sd[nt][1], src1);
            float y2 = __shfl_sync(FULLMASK, sd[nt][2], src1);
            float y3 = __shfl_sync(FULLMASK, sd[nt][3], src1);
            ea[nt][0] = __float_as_uint(to_tf32(odd ? x1 : x0));
            ea[nt][1] = __float_as_uint(to_tf32(odd ? x3 : x2));
            ea[nt][2] = __float_as_uint(to_tf32(odd ? y1 : y0));
            ea[nt][3] = __float_as_uint(to_tf32(odd ? y3 : y2));
        }

        // ---- ctx += E_norm . V ----
        #pragma unroll
        for (int nt = 0; nt < 4; ++nt) {
            int kr = ng * 32 + nt * 8;
            #pragma unroll
            for (int ct = 0; ct < 8; ++ct) {
                unsigned b0 = ldu(&Vs[(kr + tg)     * LDV + ct * 8 + grp]);
                unsigned b1 = ldu(&Vs[(kr + tg + 4) * LDV + ct * 8 + grp]);
                mma_tf32(ctxa[ct], ea[nt], b0, b1);
            }
        }
        __syncthreads();   // all warps' staged e visible; tile reads done

        // ---- coalesced streaming write of normalized attn tile ----
        {
            float* ag = Ab + kt * TK;
            #pragma unroll
            for (int it = 0; it < 4; ++it) {
                int idx = tid + it * 256;
                int r = idx >> 4, c4 = (idx & 15) << 2;
                float4 v = *(float4*)&Ms[r * LDM + c4];
                __stcs((float4*)(ag + (size_t)r * SEQ + c4), v);
            }
        }
        __syncthreads();   // staging reads done before next cp.async overwrites
    }

    // ---- ctx 2-way partial reduction (ng=0 stages, ng=1 adds + writes) ----
    float* ctxbuf = dynsm;   // tile buffers dead
    if (ng == 0) {
        #pragma unroll
        for (int ct = 0; ct < 8; ++ct) {
            int c = ct * 8 + 2 * tg;
            *(float2*)&ctxbuf[row0 * LDC + c] = make_float2(ctxa[ct][0], ctxa[ct][1]);
            *(float2*)&ctxbuf[row1 * LDC + c] = make_float2(ctxa[ct][2], ctxa[ct][3]);
        }
    }
    __syncthreads();
    if (ng == 1) {
        #pragma unroll
        for (int ct = 0; ct < 8; ++ct) {
            int c = ct * 8 + 2 * tg;
            float2 p0 = *(float2*)&ctxbuf[row0 * LDC + c];
            float2 p1 = *(float2*)&ctxbuf[row1 * LDC + c];
            *(float2*)(Cb + (size_t)row0 * DK + c) =
                make_float2(p0.x + ctxa[ct][0], p0.y + ctxa[ct][1]);
            *(float2*)(Cb + (size_t)row1 * DK + c) =
                make_float2(p1.x + ctxa[ct][2], p1.y + ctxa[ct][3]);
        }
    }
}

extern "C" void kernel_launch(void* const* d_in, const int* in_sizes, int n_in,
                              void* d_out, int out_size)
{
    const float* Q = (const float*)d_in[0];
    const float* K = (const float*)d_in[1];
    const float* V = (const float*)d_in[2];
    const float* M = (const float*)d_in[3];

    float* ctx  = (float*)d_out;                                    // B*H*S*DK
    float* attn = (float*)d_out + (size_t)BATCH * HEADS * SEQ * DK; // B*H*S*S

    // pass 0: pre-round K,V to tf32 into __device__ scratch
    prep_kernel<<<(2 * (KV_ELEMS / 4) + 255) / 256, 256>>>(K, V);

    const size_t smem = (size_t)(2 * TK * LDK + 2 * TK * LDV + 2 * TQ * LDM)
                        * sizeof(float);                            // 106496 B
    cudaFuncSetAttribute(attn_kernel, cudaFuncAttributeMaxDynamicSharedMemorySize, (int)smem);

    dim3 grid(SEQ / TQ, HEADS, BATCH);
    attn_kernel<<<grid, 256, smem>>>(Q, M, ctx, attn);
}